// round 2
// baseline (speedup 1.0000x reference)
#include <cuda_runtime.h>
#include <math.h>

// ---------------------------------------------------------------------------
// Shapes: N=16, F=5, V=4 -> 320 images of 3x224x224
// conv1: 3->3, 3x3, s2: 224->111 ; maxpool3/3 -> 37 ; relu
// conv2: 3->1, 3x3, s2: 37->18   ; maxpool3/3 -> 6  ; relu
// flatten 36 -> linear -> feat[320,6]; graph ops + MLP -> [16,6]
// ---------------------------------------------------------------------------

#define NIMG 320
#define H1_STRIDE (3 * 37 * 37)

__device__ float g_h1[NIMG * H1_STRIDE];
__device__ float g_feat[NIMG * 6];

// ---------------------------------------------------------------------------
// Kernel 1: fused conv1(s2) + maxpool3 + relu, smem-tiled.
// Block = (img, band of 2 pooled rows). Tile = 3ch x 13rows x 224 cols
// loaded as coalesced float4 (34.9 KB smem). 74 threads then each compute one
// (py_local, px): 9 conv positions x 27 FMA reading smem, running max.
// ---------------------------------------------------------------------------
#define BANDS 19   // ceil(37/2)

__global__ __launch_bounds__(256)
void conv1_pool_kernel(const float* __restrict__ nodes,
                       const float* __restrict__ w,   // [3,3,3,3] OIHW
                       const float* __restrict__ b)   // [3]
{
    __shared__ float tile[3][13 * 224];   // 34.9 KB
    __shared__ float sw[81];
    __shared__ float sb[3];

    int t = threadIdx.x;
    if (t < 81) sw[t] = w[t];
    if (t < 3)  sb[t] = b[t];

    int blk  = blockIdx.x;
    int band = blk % BANDS;
    int img  = blk / BANDS;
    int py0  = band * 2;
    int nrowsP = (py0 + 2 <= 37) ? 2 : (37 - py0);   // 2 or 1
    int in_r0  = py0 * 6;
    int nrowsI = 6 * nrowsP + 1;                      // 13 or 7

    // Cooperative coalesced float4 tile load (rows are 224 floats, 16B-aligned)
    const float* src = nodes + (size_t)img * (3 * 224 * 224);
    int total4 = 3 * nrowsI * 56;
    for (int i = t; i < total4; i += 256) {
        int ch  = i / (nrowsI * 56);
        int rem = i - ch * (nrowsI * 56);
        int rr  = rem / 56;
        int c4  = rem - rr * 56;
        float4 v = *(const float4*)(src + (size_t)ch * 50176
                                        + (size_t)(in_r0 + rr) * 224 + c4 * 4);
        *(float4*)&tile[ch][rr * 224 + c4 * 4] = v;
    }
    __syncthreads();

    int outs = nrowsP * 37;
    if (t < outs) {
        int pyl = t / 37;
        int px  = t - pyl * 37;
        int br  = pyl * 6;       // base input row within tile
        int bc  = px * 6;        // base input col

        float m0 = -1e30f, m1 = -1e30f, m2 = -1e30f;
#pragma unroll
        for (int cy = 0; cy < 3; cy++)
#pragma unroll
            for (int cx = 0; cx < 3; cx++) {
                float s0 = sb[0], s1 = sb[1], s2 = sb[2];
#pragma unroll
                for (int ic = 0; ic < 3; ic++)
#pragma unroll
                    for (int ky = 0; ky < 3; ky++)
#pragma unroll
                        for (int kx = 0; kx < 3; kx++) {
                            float v = tile[ic][(br + 2 * cy + ky) * 224
                                               + bc + 2 * cx + kx];
                            int kidx = ic * 9 + ky * 3 + kx;
                            s0 += v * sw[kidx];
                            s1 += v * sw[27 + kidx];
                            s2 += v * sw[54 + kidx];
                        }
                m0 = fmaxf(m0, s0);
                m1 = fmaxf(m1, s1);
                m2 = fmaxf(m2, s2);
            }
        int py = py0 + pyl;
        float* dst = g_h1 + (size_t)img * H1_STRIDE + py * 37 + px;
        dst[0]        = fmaxf(m0, 0.0f);
        dst[1369]     = fmaxf(m1, 0.0f);
        dst[2 * 1369] = fmaxf(m2, 0.0f);
    }
}

// ---------------------------------------------------------------------------
// Kernel 2: fused conv2(s2) + maxpool3 + relu + 36->6 linear.
// One block per image, 324 threads: one per (pool_output 0..35, conv_pos 0..8).
// Each does an unrolled 27-FMA dot (L2-resident loads), then 9-way max + matvec.
// ---------------------------------------------------------------------------
__global__ __launch_bounds__(324)
void conv2_feat_kernel(const float* __restrict__ c2w,  // [1,3,3,3]
                       const float* __restrict__ c2b,  // [1]
                       const float* __restrict__ lw,   // [36,6]
                       const float* __restrict__ lb)   // [6]
{
    __shared__ float sconv[36][9];
    __shared__ float hs[36];
    __shared__ float w[27];
    int img = blockIdx.x;
    int t   = threadIdx.x;
    if (t < 27) w[t] = c2w[t];
    __syncthreads();

    {
        int pool = t / 9, pos = t - pool * 9;
        int py = pool / 6, px = pool - py * 6;
        int cy = 3 * py + pos / 3;
        int cx = 3 * px + pos % 3;
        const float* src = g_h1 + (size_t)img * H1_STRIDE + (2 * cy) * 37 + 2 * cx;
        float s = __ldg(c2b);
#pragma unroll
        for (int ic = 0; ic < 3; ic++)
#pragma unroll
            for (int ky = 0; ky < 3; ky++)
#pragma unroll
                for (int kx = 0; kx < 3; kx++)
                    s += __ldg(src + ic * 1369 + ky * 37 + kx) * w[ic * 9 + ky * 3 + kx];
        sconv[pool][pos] = s;
    }
    __syncthreads();

    if (t < 36) {
        float m = sconv[t][0];
#pragma unroll
        for (int p = 1; p < 9; p++) m = fmaxf(m, sconv[t][p]);
        hs[t] = fmaxf(m, 0.0f);
    }
    __syncthreads();

    if (t < 6) {
        float s = __ldg(lb + t);
#pragma unroll
        for (int i = 0; i < 36; i++) s += hs[i] * __ldg(lw + i * 6 + t);
        g_feat[img * 6 + t] = s;
    }
}

// ---------------------------------------------------------------------------
// Kernel 3: graph ops + readout MLP. One block per sample (16 blocks).
// wfc_w [24,1] decomposes: link[s][t] = sigmoid(asrc[s] + btgt[t] + b).
// ---------------------------------------------------------------------------
__global__ __launch_bounds__(128)
void graph_readout_kernel(const float* __restrict__ pos,     // [16,5,4,6]
                          const float* __restrict__ attmap,  // [16,5,4,4]
                          const float* __restrict__ wfc_w,
                          const float* __restrict__ wfc_b,
                          const float* __restrict__ fm_w,
                          const float* __restrict__ fm_b,
                          const float* __restrict__ lm_w,
                          const float* __restrict__ lm_b,
                          const float* __restrict__ fc1_w,   // [240,120]
                          const float* __restrict__ fc1_b,
                          const float* __restrict__ fc2_w,   // [120,60]
                          const float* __restrict__ fc2_b,
                          const float* __restrict__ fc3_w,   // [60,6]
                          const float* __restrict__ fc3_b,
                          float* __restrict__ out)           // [16,6]
{
    int n = blockIdx.x;
    int t = threadIdx.x;

    __shared__ float feat[20][6];
    __shared__ float ps[20][6];
    __shared__ float asrc[20];
    __shared__ float btgt[20];
    __shared__ float pm[20][6];
    __shared__ float inp[240];
    __shared__ float r1[120];
    __shared__ float r2[60];

    if (t < 120) {
        int fv = t / 6, d = t % 6;
        feat[fv][d] = g_feat[(n * 20 + fv) * 6 + d];
        ps[fv][d]   = pos[(n * 20 + fv) * 6 + d];
    }
    __syncthreads();

    if (t < 20) {
        float a = 0.0f, bb = 0.0f;
#pragma unroll
        for (int k = 0; k < 6; k++) {
            a  += feat[t][k] * wfc_w[k]      + ps[t][k] * wfc_w[6 + k];
            bb += feat[t][k] * wfc_w[12 + k] + ps[t][k] * wfc_w[18 + k];
        }
        asrc[t] = a;
        btgt[t] = bb;
    }
    if (t < 120) {
        int fv = t / 6, d = t % 6;
        float s = fm_b[d];
#pragma unroll
        for (int k = 0; k < 6; k++) s += ps[fv][k] * fm_w[k * 6 + d];
        pm[fv][d] = s;
    }
    __syncthreads();

    if (t < 120) {
        int fv = t / 6, d = t % 6;
        int f = fv / 4, tv = fv % 4;
        float bias = wfc_b[0];
        float agg = 0.0f;
#pragma unroll
        for (int s = 0; s < 4; s++) {
            float z  = asrc[f * 4 + s] + btgt[f * 4 + tv] + bias;
            float lk = 1.0f / (1.0f + expf(-z));
            float m  = lk + attmap[((n * 5 + f) * 4 + s) * 4 + tv];
            agg += m * pm[f * 4 + s][d];
        }
        if (f > 0) {
            float lm = lm_b[d];
#pragma unroll
            for (int k = 0; k < 6; k++) lm += ps[(f - 1) * 4 + tv][k] * lm_w[k * 6 + d];
            agg += lm;
        }
        inp[fv * 12 + d]     = feat[fv][d];
        inp[fv * 12 + 6 + d] = agg;
    }
    __syncthreads();

    if (t < 120) {
        float s = fc1_b[t];
#pragma unroll 8
        for (int i = 0; i < 240; i++) s += inp[i] * fc1_w[i * 120 + t];
        r1[t] = fmaxf(s, 0.0f);
    }
    __syncthreads();
    if (t < 60) {
        float s = fc2_b[t];
#pragma unroll 8
        for (int i = 0; i < 120; i++) s += r1[i] * fc2_w[i * 60 + t];
        r2[t] = fmaxf(s, 0.0f);
    }
    __syncthreads();
    if (t < 6) {
        float s = fc3_b[t];
#pragma unroll
        for (int i = 0; i < 60; i++) s += r2[i] * fc3_w[i * 6 + t];
        out[n * 6 + t] = s;
    }
}

// ---------------------------------------------------------------------------
extern "C" void kernel_launch(void* const* d_in, const int* in_sizes, int n_in,
                              void* d_out, int out_size)
{
    const float* nodes   = (const float*)d_in[0];
    const float* pos     = (const float*)d_in[1];
    const float* attmap  = (const float*)d_in[2];
    const float* conv1_w = (const float*)d_in[4];
    const float* conv1_b = (const float*)d_in[5];
    const float* conv2_w = (const float*)d_in[6];
    const float* conv2_b = (const float*)d_in[7];
    const float* lin_w   = (const float*)d_in[8];
    const float* lin_b   = (const float*)d_in[9];
    const float* wfc_w   = (const float*)d_in[10];
    const float* wfc_b   = (const float*)d_in[11];
    const float* fm_w    = (const float*)d_in[12];
    const float* fm_b    = (const float*)d_in[13];
    const float* lm_w    = (const float*)d_in[14];
    const float* lm_b    = (const float*)d_in[15];
    const float* fc1_w   = (const float*)d_in[16];
    const float* fc1_b   = (const float*)d_in[17];
    const float* fc2_w   = (const float*)d_in[18];
    const float* fc2_b   = (const float*)d_in[19];
    const float* fc3_w   = (const float*)d_in[20];
    const float* fc3_b   = (const float*)d_in[21];
    float* out = (float*)d_out;

    conv1_pool_kernel<<<NIMG * BANDS, 256>>>(nodes, conv1_w, conv1_b);
    conv2_feat_kernel<<<NIMG, 324>>>(conv2_w, conv2_b, lin_w, lin_b);
    graph_readout_kernel<<<16, 128>>>(pos, attmap, wfc_w, wfc_b, fm_w, fm_b,
                                      lm_w, lm_b, fc1_w, fc1_b, fc2_w, fc2_b,
                                      fc3_w, fc3_b, out);
}

// round 3
// speedup vs baseline: 1.1498x; 1.1498x over previous
#include <cuda_runtime.h>
#include <math.h>

// ---------------------------------------------------------------------------
// Shapes: N=16, F=5, V=4 -> 320 images of 3x224x224
// conv1: 3->3, 3x3, s2: 224->111 ; maxpool3/3 -> 37 ; relu
// conv2: 3->1, 3x3, s2: 37->18   ; maxpool3/3 -> 6  ; relu
// flatten 36 -> linear -> feat[320,6]; graph ops + MLP -> [16,6]
// ---------------------------------------------------------------------------

#define NIMG 320
#define H1_STRIDE (3 * 37 * 37)

__device__ float g_h1[NIMG * H1_STRIDE];
__device__ float g_feat[NIMG * 6];

// ---------------------------------------------------------------------------
// Kernel 1: fused conv1(s2) + maxpool3 + relu.
// One thread per (img, py, px) — independent threads, no syncs (best overlap,
// per R1 vs R2 measurement). Row-streaming: load each of the 21 (ch,row) input
// rows as 3xfloat2 + 1xfloat (8B-aligned), immediately accumulate into the
// 9 conv positions x 3 output channels. 84 LDGs/thread (vs 147 scalar in R1)
// -> 1.75x fewer L1 wavefronts; ~28 live accumulator regs (vs 49-reg patch).
// ---------------------------------------------------------------------------
__global__ __launch_bounds__(256)
void conv1_pool_kernel(const float* __restrict__ nodes,
                       const float* __restrict__ w,   // [3,3,3,3] OIHW
                       const float* __restrict__ b)   // [3]
{
    __shared__ float sw[81];
    __shared__ float sb[3];
    int tid = threadIdx.x;
    if (tid < 81) sw[tid] = w[tid];
    if (tid < 3)  sb[tid] = b[tid];
    __syncthreads();

    int idx = blockIdx.x * 256 + tid;
    if (idx >= NIMG * 37 * 37) return;
    int px  = idx % 37;
    int rem = idx / 37;
    int py  = rem % 37;
    int img = rem / 37;

    const float* base = nodes + (size_t)img * 150528
                              + (size_t)(6 * py) * 224 + 6 * px;

    float acc[9][3];
#pragma unroll
    for (int p = 0; p < 9; p++) {
        acc[p][0] = sb[0]; acc[p][1] = sb[1]; acc[p][2] = sb[2];
    }

#pragma unroll
    for (int ic = 0; ic < 3; ic++) {
        const float* chan = base + ic * 50176;
#pragma unroll
        for (int r = 0; r < 7; r++) {
            const float* rp = chan + r * 224;
            float2 v01 = *(const float2*)(rp);
            float2 v23 = *(const float2*)(rp + 2);
            float2 v45 = *(const float2*)(rp + 4);
            float  v6  = __ldg(rp + 6);
            float row[7];
            row[0] = v01.x; row[1] = v01.y; row[2] = v23.x; row[3] = v23.y;
            row[4] = v45.x; row[5] = v45.y; row[6] = v6;

            // conv output rows cy receiving this input row: ky = r - 2cy in [0,2]
#pragma unroll
            for (int cy = 0; cy < 3; cy++) {
                int ky = r - 2 * cy;
                if (ky < 0 || ky > 2) continue;   // compile-time resolved
#pragma unroll
                for (int cx = 0; cx < 3; cx++)
#pragma unroll
                    for (int kx = 0; kx < 3; kx++) {
                        float v = row[2 * cx + kx];
                        int widx = ic * 9 + ky * 3 + kx;
                        acc[cy * 3 + cx][0] += v * sw[widx];
                        acc[cy * 3 + cx][1] += v * sw[27 + widx];
                        acc[cy * 3 + cx][2] += v * sw[54 + widx];
                    }
            }
        }
    }

#pragma unroll
    for (int oc = 0; oc < 3; oc++) {
        float m = acc[0][oc];
#pragma unroll
        for (int p = 1; p < 9; p++) m = fmaxf(m, acc[p][oc]);
        m = fmaxf(m, 0.0f);
        g_h1[(size_t)img * H1_STRIDE + oc * 1369 + py * 37 + px] = m;
    }
}

// ---------------------------------------------------------------------------
// Kernel 2: fused conv2(s2) + maxpool3 + relu + 36->6 linear.
// One block per image, 324 threads: one per (pool_output 0..35, conv_pos 0..8).
// 27-FMA unrolled dot (g_h1 is L2-resident), 9-way max, then matvec.
// ---------------------------------------------------------------------------
__global__ __launch_bounds__(324)
void conv2_feat_kernel(const float* __restrict__ c2w,  // [1,3,3,3]
                       const float* __restrict__ c2b,  // [1]
                       const float* __restrict__ lw,   // [36,6]
                       const float* __restrict__ lb)   // [6]
{
    __shared__ float sconv[36][9];
    __shared__ float hs[36];
    __shared__ float w[27];
    int img = blockIdx.x;
    int t   = threadIdx.x;
    if (t < 27) w[t] = c2w[t];
    __syncthreads();

    {
        int pool = t / 9, pos = t - pool * 9;
        int py = pool / 6, px = pool - py * 6;
        int cy = 3 * py + pos / 3;
        int cx = 3 * px + pos % 3;
        const float* src = g_h1 + (size_t)img * H1_STRIDE + (2 * cy) * 37 + 2 * cx;
        float s = __ldg(c2b);
#pragma unroll
        for (int ic = 0; ic < 3; ic++)
#pragma unroll
            for (int ky = 0; ky < 3; ky++)
#pragma unroll
                for (int kx = 0; kx < 3; kx++)
                    s += __ldg(src + ic * 1369 + ky * 37 + kx) * w[ic * 9 + ky * 3 + kx];
        sconv[pool][pos] = s;
    }
    __syncthreads();

    if (t < 36) {
        float m = sconv[t][0];
#pragma unroll
        for (int p = 1; p < 9; p++) m = fmaxf(m, sconv[t][p]);
        hs[t] = fmaxf(m, 0.0f);
    }
    __syncthreads();

    if (t < 6) {
        float s = __ldg(lb + t);
#pragma unroll
        for (int i = 0; i < 36; i++) s += hs[i] * __ldg(lw + i * 6 + t);
        g_feat[img * 6 + t] = s;
    }
}

// ---------------------------------------------------------------------------
// Kernel 3: graph ops + readout MLP. One block per sample (16 blocks).
// wfc_w [24,1] decomposes: link[s][t] = sigmoid(asrc[s] + btgt[t] + b).
// ---------------------------------------------------------------------------
__global__ __launch_bounds__(128)
void graph_readout_kernel(const float* __restrict__ pos,     // [16,5,4,6]
                          const float* __restrict__ attmap,  // [16,5,4,4]
                          const float* __restrict__ wfc_w,
                          const float* __restrict__ wfc_b,
                          const float* __restrict__ fm_w,
                          const float* __restrict__ fm_b,
                          const float* __restrict__ lm_w,
                          const float* __restrict__ lm_b,
                          const float* __restrict__ fc1_w,   // [240,120]
                          const float* __restrict__ fc1_b,
                          const float* __restrict__ fc2_w,   // [120,60]
                          const float* __restrict__ fc2_b,
                          const float* __restrict__ fc3_w,   // [60,6]
                          const float* __restrict__ fc3_b,
                          float* __restrict__ out)           // [16,6]
{
    int n = blockIdx.x;
    int t = threadIdx.x;

    __shared__ float feat[20][6];
    __shared__ float ps[20][6];
    __shared__ float asrc[20];
    __shared__ float btgt[20];
    __shared__ float pm[20][6];
    __shared__ float inp[240];
    __shared__ float r1[120];
    __shared__ float r2[60];

    if (t < 120) {
        int fv = t / 6, d = t % 6;
        feat[fv][d] = g_feat[(n * 20 + fv) * 6 + d];
        ps[fv][d]   = pos[(n * 20 + fv) * 6 + d];
    }
    __syncthreads();

    if (t < 20) {
        float a = 0.0f, bb = 0.0f;
#pragma unroll
        for (int k = 0; k < 6; k++) {
            a  += feat[t][k] * wfc_w[k]      + ps[t][k] * wfc_w[6 + k];
            bb += feat[t][k] * wfc_w[12 + k] + ps[t][k] * wfc_w[18 + k];
        }
        asrc[t] = a;
        btgt[t] = bb;
    }
    if (t < 120) {
        int fv = t / 6, d = t % 6;
        float s = fm_b[d];
#pragma unroll
        for (int k = 0; k < 6; k++) s += ps[fv][k] * fm_w[k * 6 + d];
        pm[fv][d] = s;
    }
    __syncthreads();

    if (t < 120) {
        int fv = t / 6, d = t % 6;
        int f = fv / 4, tv = fv % 4;
        float bias = wfc_b[0];
        float agg = 0.0f;
#pragma unroll
        for (int s = 0; s < 4; s++) {
            float z  = asrc[f * 4 + s] + btgt[f * 4 + tv] + bias;
            float lk = 1.0f / (1.0f + expf(-z));
            float m  = lk + attmap[((n * 5 + f) * 4 + s) * 4 + tv];
            agg += m * pm[f * 4 + s][d];
        }
        if (f > 0) {
            float lm = lm_b[d];
#pragma unroll
            for (int k = 0; k < 6; k++) lm += ps[(f - 1) * 4 + tv][k] * lm_w[k * 6 + d];
            agg += lm;
        }
        inp[fv * 12 + d]     = feat[fv][d];
        inp[fv * 12 + 6 + d] = agg;
    }
    __syncthreads();

    if (t < 120) {
        float s = fc1_b[t];
#pragma unroll 8
        for (int i = 0; i < 240; i++) s += inp[i] * fc1_w[i * 120 + t];
        r1[t] = fmaxf(s, 0.0f);
    }
    __syncthreads();
    if (t < 60) {
        float s = fc2_b[t];
#pragma unroll 8
        for (int i = 0; i < 120; i++) s += r1[i] * fc2_w[i * 60 + t];
        r2[t] = fmaxf(s, 0.0f);
    }
    __syncthreads();
    if (t < 6) {
        float s = fc3_b[t];
#pragma unroll
        for (int i = 0; i < 60; i++) s += r2[i] * fc3_w[i * 6 + t];
        out[n * 6 + t] = s;
    }
}

// ---------------------------------------------------------------------------
extern "C" void kernel_launch(void* const* d_in, const int* in_sizes, int n_in,
                              void* d_out, int out_size)
{
    const float* nodes   = (const float*)d_in[0];
    const float* pos     = (const float*)d_in[1];
    const float* attmap  = (const float*)d_in[2];
    const float* conv1_w = (const float*)d_in[4];
    const float* conv1_b = (const float*)d_in[5];
    const float* conv2_w = (const float*)d_in[6];
    const float* conv2_b = (const float*)d_in[7];
    const float* lin_w   = (const float*)d_in[8];
    const float* lin_b   = (const float*)d_in[9];
    const float* wfc_w   = (const float*)d_in[10];
    const float* wfc_b   = (const float*)d_in[11];
    const float* fm_w    = (const float*)d_in[12];
    const float* fm_b    = (const float*)d_in[13];
    const float* lm_w    = (const float*)d_in[14];
    const float* lm_b    = (const float*)d_in[15];
    const float* fc1_w   = (const float*)d_in[16];
    const float* fc1_b   = (const float*)d_in[17];
    const float* fc2_w   = (const float*)d_in[18];
    const float* fc2_b   = (const float*)d_in[19];
    const float* fc3_w   = (const float*)d_in[20];
    const float* fc3_b   = (const float*)d_in[21];
    float* out = (float*)d_out;

    int total1 = NIMG * 37 * 37;
    conv1_pool_kernel<<<(total1 + 255) / 256, 256>>>(nodes, conv1_w, conv1_b);
    conv2_feat_kernel<<<NIMG, 324>>>(conv2_w, conv2_b, lin_w, lin_b);
    graph_readout_kernel<<<16, 128>>>(pos, attmap, wfc_w, wfc_b, fm_w, fm_b,
                                      lm_w, lm_b, fc1_w, fc1_b, fc2_w, fc2_b,
                                      fc3_w, fc3_b, out);
}

// round 4
// speedup vs baseline: 1.2190x; 1.0602x over previous
#include <cuda_runtime.h>
#include <math.h>

// ---------------------------------------------------------------------------
// Shapes: N=16, F=5, V=4 -> 320 images of 3x224x224
// conv1: 3->3, 3x3, s2: 224->111 ; maxpool3/3 -> 37 ; relu
// conv2: 3->1, 3x3, s2: 37->18   ; maxpool3/3 -> 6  ; relu
// flatten 36 -> linear -> feat[320,6]; graph ops + MLP -> [16,6]
// ---------------------------------------------------------------------------

#define NIMG 320
#define H1_STRIDE (3 * 37 * 37)

__device__ float g_h1[NIMG * H1_STRIDE];
__device__ float g_feat[NIMG * 6];

// ---------------------------------------------------------------------------
// Kernel 1: fused conv1(s2) + maxpool3 + relu.
// One thread per (img, py, px), independent (no block sync). Per channel:
// prefetch the full 7x7 patch as 4 float2 loads per row (28 independent loads
// in flight = R1's MLP) with float2 width (R3's L1 wavefront relief), then
// 243 FMAs into acc[9][3]. launch_bounds(256,3) caps regs at 85 (>=24 warps).
// Patch base col = 6*px*4B, a multiple of 8 -> float2 aligned; rp+6 reads
// cols 6,7 (in-bounds: max col 222,223).
// ---------------------------------------------------------------------------
__global__ __launch_bounds__(256, 3)
void conv1_pool_kernel(const float* __restrict__ nodes,
                       const float* __restrict__ w,   // [3,3,3,3] OIHW
                       const float* __restrict__ b)   // [3]
{
    __shared__ float sw[81];
    __shared__ float sb[3];
    int tid = threadIdx.x;
    if (tid < 81) sw[tid] = w[tid];
    if (tid < 3)  sb[tid] = b[tid];
    __syncthreads();

    int idx = blockIdx.x * 256 + tid;
    if (idx >= NIMG * 37 * 37) return;
    int px  = idx % 37;
    int rem = idx / 37;
    int py  = rem % 37;
    int img = rem / 37;

    const float* base = nodes + (size_t)img * 150528
                              + (size_t)(6 * py) * 224 + 6 * px;

    float acc[9][3];
#pragma unroll
    for (int p = 0; p < 9; p++) {
        acc[p][0] = sb[0]; acc[p][1] = sb[1]; acc[p][2] = sb[2];
    }

#pragma unroll
    for (int ic = 0; ic < 3; ic++) {
        const float* chan = base + ic * 50176;
        // Batched vectorized patch prefetch: 28 independent float2 loads.
        float2 p2[7][4];
#pragma unroll
        for (int r = 0; r < 7; r++) {
            const float* rp = chan + r * 224;
            p2[r][0] = *(const float2*)(rp);
            p2[r][1] = *(const float2*)(rp + 2);
            p2[r][2] = *(const float2*)(rp + 4);
            p2[r][3] = *(const float2*)(rp + 6);
        }

#pragma unroll
        for (int ky = 0; ky < 3; ky++)
#pragma unroll
            for (int kx = 0; kx < 3; kx++) {
                float w0 = sw[ic * 9 + ky * 3 + kx];
                float w1 = sw[27 + ic * 9 + ky * 3 + kx];
                float w2 = sw[54 + ic * 9 + ky * 3 + kx];
#pragma unroll
                for (int cy = 0; cy < 3; cy++)
#pragma unroll
                    for (int cx = 0; cx < 3; cx++) {
                        int col = 2 * cx + kx;           // 0..6
                        float v = (col & 1)
                                ? p2[2 * cy + ky][col >> 1].y
                                : p2[2 * cy + ky][col >> 1].x;
                        acc[cy * 3 + cx][0] += v * w0;
                        acc[cy * 3 + cx][1] += v * w1;
                        acc[cy * 3 + cx][2] += v * w2;
                    }
            }
    }

#pragma unroll
    for (int oc = 0; oc < 3; oc++) {
        float m = acc[0][oc];
#pragma unroll
        for (int p = 1; p < 9; p++) m = fmaxf(m, acc[p][oc]);
        m = fmaxf(m, 0.0f);
        g_h1[(size_t)img * H1_STRIDE + oc * 1369 + py * 37 + px] = m;
    }
}

// ---------------------------------------------------------------------------
// Kernel 2: fused conv2(s2) + maxpool3 + relu + 36->6 linear.
// One block per image, 324 threads: one per (pool_output 0..35, conv_pos 0..8).
// ---------------------------------------------------------------------------
__global__ __launch_bounds__(324)
void conv2_feat_kernel(const float* __restrict__ c2w,  // [1,3,3,3]
                       const float* __restrict__ c2b,  // [1]
                       const float* __restrict__ lw,   // [36,6]
                       const float* __restrict__ lb)   // [6]
{
    __shared__ float sconv[36][9];
    __shared__ float hs[36];
    __shared__ float w[27];
    int img = blockIdx.x;
    int t   = threadIdx.x;
    if (t < 27) w[t] = c2w[t];
    __syncthreads();

    {
        int pool = t / 9, pos = t - pool * 9;
        int py = pool / 6, px = pool - py * 6;
        int cy = 3 * py + pos / 3;
        int cx = 3 * px + pos % 3;
        const float* src = g_h1 + (size_t)img * H1_STRIDE + (2 * cy) * 37 + 2 * cx;
        float s = __ldg(c2b);
#pragma unroll
        for (int ic = 0; ic < 3; ic++)
#pragma unroll
            for (int ky = 0; ky < 3; ky++)
#pragma unroll
                for (int kx = 0; kx < 3; kx++)
                    s += __ldg(src + ic * 1369 + ky * 37 + kx) * w[ic * 9 + ky * 3 + kx];
        sconv[pool][pos] = s;
    }
    __syncthreads();

    if (t < 36) {
        float m = sconv[t][0];
#pragma unroll
        for (int p = 1; p < 9; p++) m = fmaxf(m, sconv[t][p]);
        hs[t] = fmaxf(m, 0.0f);
    }
    __syncthreads();

    if (t < 6) {
        float s = __ldg(lb + t);
#pragma unroll
        for (int i = 0; i < 36; i++) s += hs[i] * __ldg(lw + i * 6 + t);
        g_feat[img * 6 + t] = s;
    }
}

// ---------------------------------------------------------------------------
// Kernel 3: graph ops + readout MLP. One block per sample (16 blocks).
// wfc_w [24,1] decomposes: link[s][t] = sigmoid(asrc[s] + btgt[t] + b).
// ---------------------------------------------------------------------------
__global__ __launch_bounds__(128)
void graph_readout_kernel(const float* __restrict__ pos,     // [16,5,4,6]
                          const float* __restrict__ attmap,  // [16,5,4,4]
                          const float* __restrict__ wfc_w,
                          const float* __restrict__ wfc_b,
                          const float* __restrict__ fm_w,
                          const float* __restrict__ fm_b,
                          const float* __restrict__ lm_w,
                          const float* __restrict__ lm_b,
                          const float* __restrict__ fc1_w,   // [240,120]
                          const float* __restrict__ fc1_b,
                          const float* __restrict__ fc2_w,   // [120,60]
                          const float* __restrict__ fc2_b,
                          const float* __restrict__ fc3_w,   // [60,6]
                          const float* __restrict__ fc3_b,
                          float* __restrict__ out)           // [16,6]
{
    int n = blockIdx.x;
    int t = threadIdx.x;

    __shared__ float feat[20][6];
    __shared__ float ps[20][6];
    __shared__ float asrc[20];
    __shared__ float btgt[20];
    __shared__ float pm[20][6];
    __shared__ float inp[240];
    __shared__ float r1[120];
    __shared__ float r2[60];

    if (t < 120) {
        int fv = t / 6, d = t % 6;
        feat[fv][d] = g_feat[(n * 20 + fv) * 6 + d];
        ps[fv][d]   = pos[(n * 20 + fv) * 6 + d];
    }
    __syncthreads();

    if (t < 20) {
        float a = 0.0f, bb = 0.0f;
#pragma unroll
        for (int k = 0; k < 6; k++) {
            a  += feat[t][k] * wfc_w[k]      + ps[t][k] * wfc_w[6 + k];
            bb += feat[t][k] * wfc_w[12 + k] + ps[t][k] * wfc_w[18 + k];
        }
        asrc[t] = a;
        btgt[t] = bb;
    }
    if (t < 120) {
        int fv = t / 6, d = t % 6;
        float s = fm_b[d];
#pragma unroll
        for (int k = 0; k < 6; k++) s += ps[fv][k] * fm_w[k * 6 + d];
        pm[fv][d] = s;
    }
    __syncthreads();

    if (t < 120) {
        int fv = t / 6, d = t % 6;
        int f = fv / 4, tv = fv % 4;
        float bias = wfc_b[0];
        float agg = 0.0f;
#pragma unroll
        for (int s = 0; s < 4; s++) {
            float z  = asrc[f * 4 + s] + btgt[f * 4 + tv] + bias;
            float lk = 1.0f / (1.0f + expf(-z));
            float m  = lk + attmap[((n * 5 + f) * 4 + s) * 4 + tv];
            agg += m * pm[f * 4 + s][d];
        }
        if (f > 0) {
            float lm = lm_b[d];
#pragma unroll
            for (int k = 0; k < 6; k++) lm += ps[(f - 1) * 4 + tv][k] * lm_w[k * 6 + d];
            agg += lm;
        }
        inp[fv * 12 + d]     = feat[fv][d];
        inp[fv * 12 + 6 + d] = agg;
    }
    __syncthreads();

    if (t < 120) {
        float s = fc1_b[t];
#pragma unroll 8
        for (int i = 0; i < 240; i++) s += inp[i] * fc1_w[i * 120 + t];
        r1[t] = fmaxf(s, 0.0f);
    }
    __syncthreads();
    if (t < 60) {
        float s = fc2_b[t];
#pragma unroll 8
        for (int i = 0; i < 120; i++) s += r1[i] * fc2_w[i * 60 + t];
        r2[t] = fmaxf(s, 0.0f);
    }
    __syncthreads();
    if (t < 6) {
        float s = fc3_b[t];
#pragma unroll
        for (int i = 0; i < 60; i++) s += r2[i] * fc3_w[i * 6 + t];
        out[n * 6 + t] = s;
    }
}

// ---------------------------------------------------------------------------
extern "C" void kernel_launch(void* const* d_in, const int* in_sizes, int n_in,
                              void* d_out, int out_size)
{
    const float* nodes   = (const float*)d_in[0];
    const float* pos     = (const float*)d_in[1];
    const float* attmap  = (const float*)d_in[2];
    const float* conv1_w = (const float*)d_in[4];
    const float* conv1_b = (const float*)d_in[5];
    const float* conv2_w = (const float*)d_in[6];
    const float* conv2_b = (const float*)d_in[7];
    const float* lin_w   = (const float*)d_in[8];
    const float* lin_b   = (const float*)d_in[9];
    const float* wfc_w   = (const float*)d_in[10];
    const float* wfc_b   = (const float*)d_in[11];
    const float* fm_w    = (const float*)d_in[12];
    const float* fm_b    = (const float*)d_in[13];
    const float* lm_w    = (const float*)d_in[14];
    const float* lm_b    = (const float*)d_in[15];
    const float* fc1_w   = (const float*)d_in[16];
    const float* fc1_b   = (const float*)d_in[17];
    const float* fc2_w   = (const float*)d_in[18];
    const float* fc2_b   = (const float*)d_in[19];
    const float* fc3_w   = (const float*)d_in[20];
    const float* fc3_b   = (const float*)d_in[21];
    float* out = (float*)d_out;

    int total1 = NIMG * 37 * 37;
    conv1_pool_kernel<<<(total1 + 255) / 256, 256>>>(nodes, conv1_w, conv1_b);
    conv2_feat_kernel<<<NIMG, 324>>>(conv2_w, conv2_b, lin_w, lin_b);
    graph_readout_kernel<<<16, 128>>>(pos, attmap, wfc_w, wfc_b, fm_w, fm_b,
                                      lm_w, lm_b, fc1_w, fc1_b, fc2_w, fc2_b,
                                      fc3_w, fc3_b, out);
}

// round 5
// speedup vs baseline: 1.3916x; 1.1416x over previous
#include <cuda_runtime.h>
#include <math.h>

// ---------------------------------------------------------------------------
// Shapes: N=16, F=5, V=4 -> 320 images of 3x224x224
// conv1: 3->3, 3x3, s2: 224->111 ; maxpool3/3 -> 37 ; relu
// conv2: 3->1, 3x3, s2: 37->18   ; maxpool3/3 -> 6  ; relu
// flatten 36 -> linear -> feat[320,6]; graph ops + MLP -> [16,6]
//
// SINGLE fused kernel: block = image. conv1+pool -> smem, conv2+pool+linear
// -> g_feat, then blocks 0..15 spin on a completion counter and each runs one
// sample's graph+readout MLP. No intermediate global tensors except g_feat
// (7.7 KB), no inter-kernel gaps.
// ---------------------------------------------------------------------------

#define NIMG 320

__device__ float g_feat[NIMG * 6];
__device__ int   g_c1 = 0;   // conv-done counter (reset by last readout block)
__device__ int   g_c2 = 0;   // readout-done counter

__global__ __launch_bounds__(256, 3)
void fused_kernel(const float* __restrict__ nodes,
                  const float* __restrict__ pos,     // [16,5,4,6]
                  const float* __restrict__ attmap,  // [16,5,4,4]
                  const float* __restrict__ c1w, const float* __restrict__ c1b,
                  const float* __restrict__ c2w, const float* __restrict__ c2b,
                  const float* __restrict__ lw,  const float* __restrict__ lb,
                  const float* __restrict__ wfc_w, const float* __restrict__ wfc_b,
                  const float* __restrict__ fm_w,  const float* __restrict__ fm_b,
                  const float* __restrict__ lm_w,  const float* __restrict__ lm_b,
                  const float* __restrict__ fc1_w, const float* __restrict__ fc1_b,
                  const float* __restrict__ fc2_w, const float* __restrict__ fc2_b,
                  const float* __restrict__ fc3_w, const float* __restrict__ fc3_b,
                  float* __restrict__ out)           // [16,6]
{
    __shared__ float s_h1[3 * 1369];   // post conv1+pool+relu, [oc][37][37]
    __shared__ float sw[81];
    __shared__ float sb[3];
    __shared__ float sw2[27];
    __shared__ float s_conv[36][9];
    __shared__ float s_hs[36];
    // readout scratch (only used by blocks 0..15)
    __shared__ float r_feat[20][6];
    __shared__ float r_ps[20][6];
    __shared__ float r_asrc[20];
    __shared__ float r_btgt[20];
    __shared__ float r_pm[20][6];
    __shared__ float r_inp[240];
    __shared__ float r_part[240];
    __shared__ float r_r1[120];
    __shared__ float r_r2[60];

    const int img = blockIdx.x;
    const int t   = threadIdx.x;

    if (t < 81) sw[t] = c1w[t];
    if (t < 3)  sb[t] = c1b[t];
    if (t >= 96 && t < 123) sw2[t - 96] = c2w[t - 96];
    __syncthreads();

    // ---------------- Phase A: conv1(s2) + maxpool3 + relu -> s_h1 ----------
    const float* ibase = nodes + (size_t)img * 150528;
    for (int o = t; o < 1369; o += 256) {
        int py = o / 37, px = o - py * 37;
        const float* base = ibase + (size_t)(6 * py) * 224 + 6 * px;

        float acc[9][3];
#pragma unroll
        for (int p = 0; p < 9; p++) {
            acc[p][0] = sb[0]; acc[p][1] = sb[1]; acc[p][2] = sb[2];
        }

#pragma unroll
        for (int ic = 0; ic < 3; ic++) {
            const float* chan = base + ic * 50176;
            float2 p2[7][4];
#pragma unroll
            for (int r = 0; r < 7; r++) {
                const float* rp = chan + r * 224;
                p2[r][0] = *(const float2*)(rp);
                p2[r][1] = *(const float2*)(rp + 2);
                p2[r][2] = *(const float2*)(rp + 4);
                p2[r][3] = *(const float2*)(rp + 6);
            }
#pragma unroll
            for (int ky = 0; ky < 3; ky++)
#pragma unroll
                for (int kx = 0; kx < 3; kx++) {
                    float w0 = sw[ic * 9 + ky * 3 + kx];
                    float w1 = sw[27 + ic * 9 + ky * 3 + kx];
                    float w2 = sw[54 + ic * 9 + ky * 3 + kx];
#pragma unroll
                    for (int cy = 0; cy < 3; cy++)
#pragma unroll
                        for (int cx = 0; cx < 3; cx++) {
                            int col = 2 * cx + kx;
                            float v = (col & 1) ? p2[2 * cy + ky][col >> 1].y
                                                : p2[2 * cy + ky][col >> 1].x;
                            acc[cy * 3 + cx][0] += v * w0;
                            acc[cy * 3 + cx][1] += v * w1;
                            acc[cy * 3 + cx][2] += v * w2;
                        }
                }
        }
#pragma unroll
        for (int oc = 0; oc < 3; oc++) {
            float m = acc[0][oc];
#pragma unroll
            for (int p = 1; p < 9; p++) m = fmaxf(m, acc[p][oc]);
            s_h1[oc * 1369 + o] = fmaxf(m, 0.0f);
        }
    }
    __syncthreads();

    // ---------------- Phase B: conv2(s2) + maxpool3 + relu + linear ---------
    for (int posn = t; posn < 324; posn += 256) {
        int pool = posn / 9, cp = posn - pool * 9;
        int py = pool / 6, px = pool - py * 6;
        int cy = 3 * py + cp / 3;
        int cx = 3 * px + cp % 3;
        const float* src = s_h1 + (2 * cy) * 37 + 2 * cx;
        float s = __ldg(c2b);
#pragma unroll
        for (int ic = 0; ic < 3; ic++)
#pragma unroll
            for (int ky = 0; ky < 3; ky++)
#pragma unroll
                for (int kx = 0; kx < 3; kx++)
                    s += src[ic * 1369 + ky * 37 + kx] * sw2[ic * 9 + ky * 3 + kx];
        s_conv[pool][cp] = s;
    }
    __syncthreads();

    if (t < 36) {
        float m = s_conv[t][0];
#pragma unroll
        for (int p = 1; p < 9; p++) m = fmaxf(m, s_conv[t][p]);
        s_hs[t] = fmaxf(m, 0.0f);
    }
    __syncthreads();

    if (t < 6) {
        float s = __ldg(lb + t);
#pragma unroll
        for (int i = 0; i < 36; i++) s += s_hs[i] * __ldg(lw + i * 6 + t);
        g_feat[img * 6 + t] = s;
        __threadfence();                 // publish before the counter add
    }
    __syncthreads();
    if (t == 0) atomicAdd(&g_c1, 1);

    if (img >= 16) return;

    // ---------------- Phase C: blocks 0..15 — graph ops + readout MLP -------
    if (t == 0) {
        while (atomicAdd(&g_c1, 0) < NIMG) __nanosleep(128);
    }
    __syncthreads();
    __threadfence();                     // acquire: g_feat of all blocks

    const int n = img;

    if (t < 120) {
        int fv = t / 6, d = t % 6;
        r_feat[fv][d] = g_feat[(n * 20 + fv) * 6 + d];
        r_ps[fv][d]   = pos[(n * 20 + fv) * 6 + d];
    }
    __syncthreads();

    if (t < 20) {
        float a = 0.0f, bb = 0.0f;
#pragma unroll
        for (int k = 0; k < 6; k++) {
            a  += r_feat[t][k] * wfc_w[k]      + r_ps[t][k] * wfc_w[6 + k];
            bb += r_feat[t][k] * wfc_w[12 + k] + r_ps[t][k] * wfc_w[18 + k];
        }
        r_asrc[t] = a;
        r_btgt[t] = bb;
    }
    if (t < 120) {
        int fv = t / 6, d = t % 6;
        float s = fm_b[d];
#pragma unroll
        for (int k = 0; k < 6; k++) s += r_ps[fv][k] * fm_w[k * 6 + d];
        r_pm[fv][d] = s;
    }
    __syncthreads();

    if (t < 120) {
        int fv = t / 6, d = t % 6;
        int f = fv / 4, tv = fv % 4;
        float bias = wfc_b[0];
        float agg = 0.0f;
#pragma unroll
        for (int s = 0; s < 4; s++) {
            float z  = r_asrc[f * 4 + s] + r_btgt[f * 4 + tv] + bias;
            float lk = 1.0f / (1.0f + expf(-z));
            float m  = lk + attmap[((n * 5 + f) * 4 + s) * 4 + tv];
            agg += m * r_pm[f * 4 + s][d];
        }
        if (f > 0) {
            float lm = lm_b[d];
#pragma unroll
            for (int k = 0; k < 6; k++) lm += r_ps[(f - 1) * 4 + tv][k] * lm_w[k * 6 + d];
            agg += lm;
        }
        r_inp[fv * 12 + d]     = r_feat[fv][d];
        r_inp[fv * 12 + 6 + d] = agg;
    }
    __syncthreads();

    // fc1: 240x120, dot split across two thread groups (halves the chain)
    if (t < 240) {
        int half = t / 120, j = t - half * 120;
        int i0 = half * 120;
        float s = 0.0f;
#pragma unroll 12
        for (int i = 0; i < 120; i++)
            s += r_inp[i0 + i] * __ldg(fc1_w + (i0 + i) * 120 + j);
        r_part[t] = s;
    }
    __syncthreads();
    if (t < 120) r_r1[t] = fmaxf(r_part[t] + r_part[120 + t] + __ldg(fc1_b + t), 0.0f);
    __syncthreads();

    // fc2: 120x60, split in two
    if (t < 120) {
        int half = t / 60, j = t - half * 60;
        int i0 = half * 60;
        float s = 0.0f;
#pragma unroll 12
        for (int i = 0; i < 60; i++)
            s += r_r1[i0 + i] * __ldg(fc2_w + (i0 + i) * 60 + j);
        r_part[t] = s;
    }
    __syncthreads();
    if (t < 60) r_r2[t] = fmaxf(r_part[t] + r_part[60 + t] + __ldg(fc2_b + t), 0.0f);
    __syncthreads();

    if (t < 6) {
        float s = __ldg(fc3_b + t);
#pragma unroll
        for (int i = 0; i < 60; i++) s += r_r2[i] * __ldg(fc3_w + i * 6 + t);
        out[n * 6 + t] = s;
    }
    __syncthreads();

    // reset counters for the next graph replay (deterministic)
    if (t == 0) {
        int o2 = atomicAdd(&g_c2, 1);
        if (o2 == 15) {
            g_c1 = 0;
            __threadfence();
            g_c2 = 0;
        }
    }
}

// ---------------------------------------------------------------------------
extern "C" void kernel_launch(void* const* d_in, const int* in_sizes, int n_in,
                              void* d_out, int out_size)
{
    const float* nodes   = (const float*)d_in[0];
    const float* pos     = (const float*)d_in[1];
    const float* attmap  = (const float*)d_in[2];
    const float* conv1_w = (const float*)d_in[4];
    const float* conv1_b = (const float*)d_in[5];
    const float* conv2_w = (const float*)d_in[6];
    const float* conv2_b = (const float*)d_in[7];
    const float* lin_w   = (const float*)d_in[8];
    const float* lin_b   = (const float*)d_in[9];
    const float* wfc_w   = (const float*)d_in[10];
    const float* wfc_b   = (const float*)d_in[11];
    const float* fm_w    = (const float*)d_in[12];
    const float* fm_b    = (const float*)d_in[13];
    const float* lm_w    = (const float*)d_in[14];
    const float* lm_b    = (const float*)d_in[15];
    const float* fc1_w   = (const float*)d_in[16];
    const float* fc1_b   = (const float*)d_in[17];
    const float* fc2_w   = (const float*)d_in[18];
    const float* fc2_b   = (const float*)d_in[19];
    const float* fc3_w   = (const float*)d_in[20];
    const float* fc3_b   = (const float*)d_in[21];
    float* out = (float*)d_out;

    fused_kernel<<<NIMG, 256>>>(nodes, pos, attmap,
                                conv1_w, conv1_b, conv2_w, conv2_b,
                                lin_w, lin_b, wfc_w, wfc_b, fm_w, fm_b,
                                lm_w, lm_b, fc1_w, fc1_b, fc2_w, fc2_b,
                                fc3_w, fc3_b, out);
}